// round 1
// baseline (speedup 1.0000x reference)
#include <cuda_runtime.h>
#include <math.h>
#include <float.h>

// Constants from the reference
#define BS 16
#define CH 64
#define NC 81
#define HW 65536          // 256*256
#define FG_STCH 1
#define NITEMS (BS * (CH - FG_STCH))   // 1008

// Scratch for per-(b,c) max of pred_mask_prob (no cudaMalloc allowed)
__device__ float g_maxprob[BS * CH];

// ---------------------------------------------------------------------------
// Kernel A: max over HW for each (b, c). One block per (b,c), float4 loads.
// ---------------------------------------------------------------------------
__global__ __launch_bounds__(256) void maxprob_kernel(const float4* __restrict__ p) {
    const int bc = blockIdx.x;                     // 0..1023
    const float4* base = p + (size_t)bc * (HW / 4);

    float m = -FLT_MAX;
#pragma unroll 4
    for (int i = threadIdx.x; i < HW / 4; i += 256) {
        float4 v = base[i];
        m = fmaxf(m, fmaxf(fmaxf(v.x, v.y), fmaxf(v.z, v.w)));
    }

    // warp reduce
#pragma unroll
    for (int o = 16; o > 0; o >>= 1)
        m = fmaxf(m, __shfl_xor_sync(0xFFFFFFFFu, m, o));

    __shared__ float sm[8];
    if ((threadIdx.x & 31) == 0) sm[threadIdx.x >> 5] = m;
    __syncthreads();
    if (threadIdx.x < 8) {
        m = sm[threadIdx.x];
#pragma unroll
        for (int o = 4; o > 0; o >>= 1)
            m = fmaxf(m, __shfl_xor_sync(0xFFu, m, o));
        if (threadIdx.x == 0) g_maxprob[bc] = m;
    }
}

// ---------------------------------------------------------------------------
// Kernel B: per-item loss terms + block reduction. One block, 1024 threads,
// one thread per (b, j) item (1008 active).
// ---------------------------------------------------------------------------
__global__ __launch_bounds__(1024) void loss_kernel(
    const float* __restrict__ cls_logits,   // (bs, ch, C)
    const float* __restrict__ iou_scores,   // (bs, ch, 1)
    const int*   __restrict__ target_ids,   // (bs, ch)
    const int*   __restrict__ map_indices,  // (bs, 2, ch)
    const float* __restrict__ map_ious,     // (bs, ch)
    const float* __restrict__ rand_vals,    // (bs, ch)
    float* __restrict__ out)                // [iou_loss, cls_loss]
{
    const int t = threadIdx.x;

    float wght   = 0.0f;
    float iou_el = 0.0f;
    float ce     = 0.0f;

    if (t < NITEMS) {
        const int b = t / (CH - FG_STCH);
        const int j = FG_STCH + (t % (CH - FG_STCH));   // 1..63

        const int pj  = map_indices[b * 2 * CH + 0 * CH + j];
        const int gj  = map_indices[b * 2 * CH + 1 * CH + j];
        const int tid = target_ids[b * CH + gj];
        const int cls = max(0, tid - FG_STCH + 1);      // == tid for FG_STCH=1

        const float iou = map_ious[b * CH + j];
        const float mp  = g_maxprob[b * CH + pj];
        const float rnd = rand_vals[b * CH + j];

        const bool remove = (mp < 0.1f) && (rnd < 0.9f);
        wght = remove ? 0.0f : (iou < 0.2f ? 1.0f : 2.0f);

        // smooth L1 on |preds_iou - iou|, theta = 0.1
        const float preds_iou = iou_scores[b * CH + pj];
        const float y = fabsf(preds_iou - iou);
        iou_el = (y < 0.1f) ? (y * y * 5.0f) : (y - 0.05f);

        // log-softmax over C=81 for gathered row
        const float* row = cls_logits + ((size_t)(b * CH + pj)) * NC;
        float mx = -FLT_MAX;
#pragma unroll
        for (int c = 0; c < NC; c++) mx = fmaxf(mx, row[c]);
        float s = 0.0f;
#pragma unroll
        for (int c = 0; c < NC; c++) s += expf(row[c] - mx);
        const float logp_cls = row[cls] - mx - logf(s);
        ce = -logp_cls;   // w[cls] == 1
    }

    // Block reduction of (wsum, sum(iou_el*wght), sum(ce*wght))
    float v0 = wght;
    float v1 = iou_el * wght;
    float v2 = ce * wght;

#pragma unroll
    for (int o = 16; o > 0; o >>= 1) {
        v0 += __shfl_xor_sync(0xFFFFFFFFu, v0, o);
        v1 += __shfl_xor_sync(0xFFFFFFFFu, v1, o);
        v2 += __shfl_xor_sync(0xFFFFFFFFu, v2, o);
    }

    __shared__ float s0[32], s1[32], s2[32];
    const int wid = t >> 5, lid = t & 31;
    if (lid == 0) { s0[wid] = v0; s1[wid] = v1; s2[wid] = v2; }
    __syncthreads();

    if (wid == 0) {
        v0 = s0[lid]; v1 = s1[lid]; v2 = s2[lid];
#pragma unroll
        for (int o = 16; o > 0; o >>= 1) {
            v0 += __shfl_xor_sync(0xFFFFFFFFu, v0, o);
            v1 += __shfl_xor_sync(0xFFFFFFFFu, v1, o);
            v2 += __shfl_xor_sync(0xFFFFFFFFu, v2, o);
        }
        if (lid == 0) {
            const float wsum = v0 + 0.0001f;
            out[0] = v1 / wsum;   // iou_loss
            out[1] = v2 / wsum;   // cls_loss
        }
    }
}

// ---------------------------------------------------------------------------
extern "C" void kernel_launch(void* const* d_in, const int* in_sizes, int n_in,
                              void* d_out, int out_size) {
    const float* cls_logits     = (const float*)d_in[0];
    const float* iou_scores     = (const float*)d_in[1];
    const int*   target_ids     = (const int*)  d_in[2];
    const int*   map_indices    = (const int*)  d_in[3];
    const float* map_ious       = (const float*)d_in[4];
    const float* pred_mask_prob = (const float*)d_in[5];
    const float* rand_vals      = (const float*)d_in[6];
    float* out = (float*)d_out;

    maxprob_kernel<<<BS * CH, 256>>>((const float4*)pred_mask_prob);
    loss_kernel<<<1, 1024>>>(cls_logits, iou_scores, target_ids, map_indices,
                             map_ious, rand_vals, out);
}

// round 2
// speedup vs baseline: 1.4731x; 1.4731x over previous
#include <cuda_runtime.h>
#include <math.h>
#include <float.h>

// Constants from the reference
#define BS 16
#define CH 64
#define NC 81
#define HW 65536          // 256*256
#define FG_STCH 1
#define JCNT (CH - FG_STCH)            // 63
#define NITEMS (BS * JCNT)             // 1008
#define NBLK_LOSS 63                   // 16 items per block
#define ITEMS_PER_BLK 16

// Scratch (no cudaMalloc allowed)
__device__ float g_maxprob[BS * CH];
__device__ float g_partial[NBLK_LOSS * 3];

// ---------------------------------------------------------------------------
// Kernel A: max over HW for each (b, c). One block per (b,c), float4 loads.
// HBM-bound: 256 MB single pass.
// ---------------------------------------------------------------------------
__global__ __launch_bounds__(256) void maxprob_kernel(const float4* __restrict__ p) {
    const int bc = blockIdx.x;                     // 0..1023
    const float4* base = p + (size_t)bc * (HW / 4);

    float m = -FLT_MAX;
#pragma unroll 8
    for (int i = threadIdx.x; i < HW / 4; i += 256) {
        float4 v = base[i];
        m = fmaxf(m, fmaxf(fmaxf(v.x, v.y), fmaxf(v.z, v.w)));
    }

#pragma unroll
    for (int o = 16; o > 0; o >>= 1)
        m = fmaxf(m, __shfl_xor_sync(0xFFFFFFFFu, m, o));

    __shared__ float sm[8];
    if ((threadIdx.x & 31) == 0) sm[threadIdx.x >> 5] = m;
    __syncthreads();
    if (threadIdx.x < 8) {
        m = sm[threadIdx.x];
#pragma unroll
        for (int o = 4; o > 0; o >>= 1)
            m = fmaxf(m, __shfl_xor_sync(0xFFu, m, o));
        if (threadIdx.x == 0) g_maxprob[bc] = m;
    }
}

// ---------------------------------------------------------------------------
// Kernel B: loss partials. One WARP per item (lanes split the 81 classes),
// 16 warps per block, 63 blocks. Each block writes a fixed partial slot
// (deterministic, no atomics).
// ---------------------------------------------------------------------------
__global__ __launch_bounds__(512) void loss_partial_kernel(
    const float* __restrict__ cls_logits,   // (bs, ch, C)
    const float* __restrict__ iou_scores,   // (bs, ch, 1)
    const int*   __restrict__ target_ids,   // (bs, ch)
    const int*   __restrict__ map_indices,  // (bs, 2, ch)
    const float* __restrict__ map_ious,     // (bs, ch)
    const float* __restrict__ rand_vals)    // (bs, ch)
{
    const int warp = threadIdx.x >> 5;      // 0..15
    const int lane = threadIdx.x & 31;
    const int item = blockIdx.x * ITEMS_PER_BLK + warp;  // 0..1007 (grid=63 exact)

    const int b = item / JCNT;
    const int j = FG_STCH + (item % JCNT);  // 1..63

    const int pj  = map_indices[b * 2 * CH + 0 * CH + j];
    const int gj  = map_indices[b * 2 * CH + 1 * CH + j];
    const int tid = target_ids[b * CH + gj];
    const int cls = max(0, tid - FG_STCH + 1);

    const float iou = map_ious[b * CH + j];
    const float mp  = g_maxprob[b * CH + pj];
    const float rnd = rand_vals[b * CH + j];

    const bool remove = (mp < 0.1f) && (rnd < 0.9f);
    const float wght = remove ? 0.0f : (iou < 0.2f ? 1.0f : 2.0f);

    const float preds_iou = iou_scores[b * CH + pj];
    const float y = fabsf(preds_iou - iou);
    const float iou_el = (y < 0.1f) ? (y * y * 5.0f) : (y - 0.05f);

    // --- warp-parallel log-softmax over C=81: lane handles c = lane + 32k ---
    const float* row = cls_logits + (size_t)(b * CH + pj) * NC;
    float x0 = row[lane];
    float x1 = row[lane + 32];
    float x2 = (lane < NC - 64) ? row[lane + 64] : -FLT_MAX;

    float mx = fmaxf(fmaxf(x0, x1), x2);
#pragma unroll
    for (int o = 16; o > 0; o >>= 1)
        mx = fmaxf(mx, __shfl_xor_sync(0xFFFFFFFFu, mx, o));

    float s = expf(x0 - mx) + expf(x1 - mx);
    if (lane < NC - 64) s += expf(x2 - mx);
#pragma unroll
    for (int o = 16; o > 0; o >>= 1)
        s += __shfl_xor_sync(0xFFFFFFFFu, s, o);

    float v0 = 0.0f, v1 = 0.0f, v2 = 0.0f;
    if (lane == 0) {
        const float ce = -(row[cls] - mx - logf(s));   // w[cls]==1
        v0 = wght;
        v1 = iou_el * wght;
        v2 = ce * wght;
    }

    // block reduce: one value per warp (lane 0)
    __shared__ float s0[ITEMS_PER_BLK], s1[ITEMS_PER_BLK], s2[ITEMS_PER_BLK];
    if (lane == 0) { s0[warp] = v0; s1[warp] = v1; s2[warp] = v2; }
    __syncthreads();

    if (warp == 0) {
        float a0 = (lane < ITEMS_PER_BLK) ? s0[lane] : 0.0f;
        float a1 = (lane < ITEMS_PER_BLK) ? s1[lane] : 0.0f;
        float a2 = (lane < ITEMS_PER_BLK) ? s2[lane] : 0.0f;
#pragma unroll
        for (int o = 8; o > 0; o >>= 1) {
            a0 += __shfl_xor_sync(0xFFFFFFFFu, a0, o);
            a1 += __shfl_xor_sync(0xFFFFFFFFu, a1, o);
            a2 += __shfl_xor_sync(0xFFFFFFFFu, a2, o);
        }
        if (lane == 0) {
            g_partial[blockIdx.x * 3 + 0] = a0;
            g_partial[blockIdx.x * 3 + 1] = a1;
            g_partial[blockIdx.x * 3 + 2] = a2;
        }
    }
}

// ---------------------------------------------------------------------------
// Kernel C: final reduce of 63 partial triples. One warp.
// ---------------------------------------------------------------------------
__global__ void final_kernel(float* __restrict__ out) {
    const int lane = threadIdx.x;   // 32 threads
    float a0 = 0.0f, a1 = 0.0f, a2 = 0.0f;
#pragma unroll
    for (int k = 0; k < 2; k++) {
        int i = lane + 32 * k;
        if (i < NBLK_LOSS) {
            a0 += g_partial[i * 3 + 0];
            a1 += g_partial[i * 3 + 1];
            a2 += g_partial[i * 3 + 2];
        }
    }
#pragma unroll
    for (int o = 16; o > 0; o >>= 1) {
        a0 += __shfl_xor_sync(0xFFFFFFFFu, a0, o);
        a1 += __shfl_xor_sync(0xFFFFFFFFu, a1, o);
        a2 += __shfl_xor_sync(0xFFFFFFFFu, a2, o);
    }
    if (lane == 0) {
        const float wsum = a0 + 0.0001f;
        out[0] = a1 / wsum;   // iou_loss
        out[1] = a2 / wsum;   // cls_loss
    }
}

// ---------------------------------------------------------------------------
extern "C" void kernel_launch(void* const* d_in, const int* in_sizes, int n_in,
                              void* d_out, int out_size) {
    const float* cls_logits     = (const float*)d_in[0];
    const float* iou_scores     = (const float*)d_in[1];
    const int*   target_ids     = (const int*)  d_in[2];
    const int*   map_indices    = (const int*)  d_in[3];
    const float* map_ious       = (const float*)d_in[4];
    const float* pred_mask_prob = (const float*)d_in[5];
    const float* rand_vals      = (const float*)d_in[6];
    float* out = (float*)d_out;

    maxprob_kernel<<<BS * CH, 256>>>((const float4*)pred_mask_prob);
    loss_partial_kernel<<<NBLK_LOSS, 512>>>(cls_logits, iou_scores, target_ids,
                                            map_indices, map_ious, rand_vals);
    final_kernel<<<1, 32>>>(out);
}

// round 3
// speedup vs baseline: 1.5307x; 1.0391x over previous
#include <cuda_runtime.h>
#include <math.h>
#include <float.h>

#define BS 16
#define CH 64
#define NC 81
#define HW 65536          // 256*256
#define FG_STCH 1
#define JCNT (CH - FG_STCH)            // 63
#define NBLK_LOSS 63
#define ITEMS_PER_BLK 16
#define SPLIT 4                        // chunks per (b,c) row
#define CHUNK (HW / 4 / SPLIT)         // float4 per chunk = 4096

// Scratch (no cudaMalloc allowed)
__device__ float g_maxprob_part[BS * CH * SPLIT];
__device__ float g_partial[NBLK_LOSS * 3];
__device__ int   g_done_count;         // zero-initialized; reset by last block each call

// ---------------------------------------------------------------------------
// Kernel A: partial max over HW for each (b,c). SPLIT blocks per (b,c) row,
// each covering a contiguous 64KB chunk. Streaming loads (read-once data).
// ---------------------------------------------------------------------------
__global__ __launch_bounds__(256) void maxprob_kernel(const float4* __restrict__ p) {
    const int blk = blockIdx.x;                    // 0..4095
    const float4* base = p + (size_t)blk * CHUNK;  // contiguous chunks

    float m0 = -FLT_MAX, m1 = -FLT_MAX, m2 = -FLT_MAX, m3 = -FLT_MAX;
    // CHUNK/256 = 16 iterations; process 4 per step with independent accumulators
#pragma unroll
    for (int i = 0; i < CHUNK / (256 * 4); i++) {
        const int base_i = i * 256 * 4 + threadIdx.x;
        float4 v0 = __ldcs(&base[base_i]);
        float4 v1 = __ldcs(&base[base_i + 256]);
        float4 v2 = __ldcs(&base[base_i + 512]);
        float4 v3 = __ldcs(&base[base_i + 768]);
        m0 = fmaxf(m0, fmaxf(fmaxf(v0.x, v0.y), fmaxf(v0.z, v0.w)));
        m1 = fmaxf(m1, fmaxf(fmaxf(v1.x, v1.y), fmaxf(v1.z, v1.w)));
        m2 = fmaxf(m2, fmaxf(fmaxf(v2.x, v2.y), fmaxf(v2.z, v2.w)));
        m3 = fmaxf(m3, fmaxf(fmaxf(v3.x, v3.y), fmaxf(v3.z, v3.w)));
    }
    float m = fmaxf(fmaxf(m0, m1), fmaxf(m2, m3));

#pragma unroll
    for (int o = 16; o > 0; o >>= 1)
        m = fmaxf(m, __shfl_xor_sync(0xFFFFFFFFu, m, o));

    __shared__ float sm[8];
    if ((threadIdx.x & 31) == 0) sm[threadIdx.x >> 5] = m;
    __syncthreads();
    if (threadIdx.x < 8) {
        m = sm[threadIdx.x];
#pragma unroll
        for (int o = 4; o > 0; o >>= 1)
            m = fmaxf(m, __shfl_xor_sync(0xFFu, m, o));
        if (threadIdx.x == 0) g_maxprob_part[blk] = m;
    }
}

// ---------------------------------------------------------------------------
// Kernel B: loss partials + fused final reduce (last block to finish does it).
// One warp per item; 16 warps/block; 63 blocks.
// ---------------------------------------------------------------------------
__global__ __launch_bounds__(512) void loss_kernel(
    const float* __restrict__ cls_logits,   // (bs, ch, C)
    const float* __restrict__ iou_scores,   // (bs, ch, 1)
    const int*   __restrict__ target_ids,   // (bs, ch)
    const int*   __restrict__ map_indices,  // (bs, 2, ch)
    const float* __restrict__ map_ious,     // (bs, ch)
    const float* __restrict__ rand_vals,    // (bs, ch)
    float* __restrict__ out)                // [iou_loss, cls_loss]
{
    const int warp = threadIdx.x >> 5;      // 0..15
    const int lane = threadIdx.x & 31;
    const int item = blockIdx.x * ITEMS_PER_BLK + warp;  // 0..1007 exact

    const int b = item / JCNT;
    const int j = FG_STCH + (item % JCNT);

    const int pj  = map_indices[b * 2 * CH + 0 * CH + j];
    const int gj  = map_indices[b * 2 * CH + 1 * CH + j];
    const int tid = target_ids[b * CH + gj];
    const int cls = max(0, tid - FG_STCH + 1);

    const float iou = map_ious[b * CH + j];
    const float rnd = rand_vals[b * CH + j];

    // combine SPLIT partial maxes
    const float* mpp = &g_maxprob_part[(b * CH + pj) * SPLIT];
    const float mp = fmaxf(fmaxf(mpp[0], mpp[1]), fmaxf(mpp[2], mpp[3]));

    const bool remove = (mp < 0.1f) && (rnd < 0.9f);
    const float wght = remove ? 0.0f : (iou < 0.2f ? 1.0f : 2.0f);

    const float preds_iou = iou_scores[b * CH + pj];
    const float y = fabsf(preds_iou - iou);
    const float iou_el = (y < 0.1f) ? (y * y * 5.0f) : (y - 0.05f);

    // warp-parallel log-softmax over C=81
    const float* row = cls_logits + (size_t)(b * CH + pj) * NC;
    float x0 = row[lane];
    float x1 = row[lane + 32];
    float x2 = (lane < NC - 64) ? row[lane + 64] : -FLT_MAX;

    float mx = fmaxf(fmaxf(x0, x1), x2);
#pragma unroll
    for (int o = 16; o > 0; o >>= 1)
        mx = fmaxf(mx, __shfl_xor_sync(0xFFFFFFFFu, mx, o));

    float s = expf(x0 - mx) + expf(x1 - mx);
    if (lane < NC - 64) s += expf(x2 - mx);
#pragma unroll
    for (int o = 16; o > 0; o >>= 1)
        s += __shfl_xor_sync(0xFFFFFFFFu, s, o);

    float v0 = 0.0f, v1 = 0.0f, v2 = 0.0f;
    if (lane == 0) {
        const float ce = -(row[cls] - mx - logf(s));
        v0 = wght;
        v1 = iou_el * wght;
        v2 = ce * wght;
    }

    __shared__ float s0[ITEMS_PER_BLK], s1[ITEMS_PER_BLK], s2[ITEMS_PER_BLK];
    if (lane == 0) { s0[warp] = v0; s1[warp] = v1; s2[warp] = v2; }
    __syncthreads();

    __shared__ bool is_last;
    if (warp == 0) {
        float a0 = (lane < ITEMS_PER_BLK) ? s0[lane] : 0.0f;
        float a1 = (lane < ITEMS_PER_BLK) ? s1[lane] : 0.0f;
        float a2 = (lane < ITEMS_PER_BLK) ? s2[lane] : 0.0f;
#pragma unroll
        for (int o = 8; o > 0; o >>= 1) {
            a0 += __shfl_xor_sync(0xFFFFFFFFu, a0, o);
            a1 += __shfl_xor_sync(0xFFFFFFFFu, a1, o);
            a2 += __shfl_xor_sync(0xFFFFFFFFu, a2, o);
        }
        if (lane == 0) {
            g_partial[blockIdx.x * 3 + 0] = a0;
            g_partial[blockIdx.x * 3 + 1] = a1;
            g_partial[blockIdx.x * 3 + 2] = a2;
            __threadfence();
            const int prev = atomicAdd(&g_done_count, 1);
            is_last = (prev == NBLK_LOSS - 1);
        }
        __syncwarp();

        // Last block to finish performs the final reduction (deterministic:
        // fixed-order sum over the completed partials array).
        if (is_last) {
            float b0 = 0.0f, b1 = 0.0f, b2 = 0.0f;
#pragma unroll
            for (int k = 0; k < 2; k++) {
                const int i = lane + 32 * k;
                if (i < NBLK_LOSS) {
                    b0 += g_partial[i * 3 + 0];
                    b1 += g_partial[i * 3 + 1];
                    b2 += g_partial[i * 3 + 2];
                }
            }
#pragma unroll
            for (int o = 16; o > 0; o >>= 1) {
                b0 += __shfl_xor_sync(0xFFFFFFFFu, b0, o);
                b1 += __shfl_xor_sync(0xFFFFFFFFu, b1, o);
                b2 += __shfl_xor_sync(0xFFFFFFFFu, b2, o);
            }
            if (lane == 0) {
                const float wsum = b0 + 0.0001f;
                out[0] = b1 / wsum;   // iou_loss
                out[1] = b2 / wsum;   // cls_loss
                g_done_count = 0;     // reset for next graph replay
            }
        }
    }
}

// ---------------------------------------------------------------------------
extern "C" void kernel_launch(void* const* d_in, const int* in_sizes, int n_in,
                              void* d_out, int out_size) {
    const float* cls_logits     = (const float*)d_in[0];
    const float* iou_scores     = (const float*)d_in[1];
    const int*   target_ids     = (const int*)  d_in[2];
    const int*   map_indices    = (const int*)  d_in[3];
    const float* map_ious       = (const float*)d_in[4];
    const float* pred_mask_prob = (const float*)d_in[5];
    const float* rand_vals      = (const float*)d_in[6];
    float* out = (float*)d_out;

    maxprob_kernel<<<BS * CH * SPLIT, 256>>>((const float4*)pred_mask_prob);
    loss_kernel<<<NBLK_LOSS, 512>>>(cls_logits, iou_scores, target_ids,
                                    map_indices, map_ious, rand_vals, out);
}